// round 3
// baseline (speedup 1.0000x reference)
#include <cuda_runtime.h>
#include <cstdint>

// MeshConv: out[e][o] = sum_k combined[e][k] * W[o][k] + b[o]
// combined = [ x(32) | sa+sb(32) | da+db(32) | |sa-sb|(32) | |da-db|(32) ]
// E = out_size/64, OUT=64, K=160.

#define TILE_E  128
#define THREADS 256
#define FSTRIDE 162   // feat row stride in floats
#define NK      160
#define WP_F2   (NK * 32)   // 5120 float2 = W packed transposed

__device__ float2 g_Wpack[WP_F2];
__device__ float2 g_bpack[32];
__device__ int    g_nbr64;   // 1 if neighbor buffer is int64, 0 if int32

__global__ void meshconv_prep(const float* __restrict__ W, const float* __restrict__ b,
                              const void* __restrict__ nbr_raw, int E) {
    int i = blockIdx.x * blockDim.x + threadIdx.x;
    if (i < WP_F2) {
        int k  = i >> 5;
        int op = i & 31;
        float lo = W[(2 * op) * NK + k];
        float hi = W[(2 * op + 1) * NK + k];
        g_Wpack[i] = make_float2(lo, hi);
    }
    if (i < 32) g_bpack[i] = make_float2(b[2 * i], b[2 * i + 1]);
    if (i == 0) {
        // Probe dtype: if genuinely int64, every value lies in [-E, E).
        // If the buffer is int32, the int64 view fuses two random indices and
        // is ~idx_hi * 2^32, far outside the range.
        const long long* p = (const long long*)nbr_raw;
        int ok = 1;
        #pragma unroll
        for (int j = 0; j < 16; j++) {
            long long v = p[j];
            if (v < -(long long)E || v >= (long long)E) ok = 0;
        }
        g_nbr64 = ok;
    }
}

// ---- packed f32x2 helpers (Blackwell; ptxas never auto-fuses these) ----
__device__ __forceinline__ unsigned long long pack2(float lo, float hi) {
    unsigned long long r;
    asm("mov.b64 %0, {%1, %2};" : "=l"(r) : "f"(lo), "f"(hi));
    return r;
}
__device__ __forceinline__ unsigned long long ffma2(unsigned long long a,
                                                    unsigned long long b,
                                                    unsigned long long c) {
    unsigned long long d;
    asm("fma.rn.f32x2 %0, %1, %2, %3;" : "=l"(d) : "l"(a), "l"(b), "l"(c));
    return d;
}
__device__ __forceinline__ float2 u2f2(unsigned long long u) {
    float2 f;
    f.x = __uint_as_float((unsigned)(u & 0xFFFFFFFFull));
    f.y = __uint_as_float((unsigned)(u >> 32));
    return f;
}

__global__ __launch_bounds__(THREADS, 1)
void meshconv_kernel(const float* __restrict__ x,
                     const void* __restrict__ nbr_raw,
                     float* __restrict__ out, int E) {
    extern __shared__ float smem[];
    float2* sWp  = (float2*)smem;                 // [0,10240) floats
    float2* sB   = (float2*)(smem + 10240);       // [10240,10304)
    float*  feat = smem + 10304;                  // feat tile

    const int tid = threadIdx.x;

    {
        const float2* gw = g_Wpack;
        #pragma unroll
        for (int i = tid; i < WP_F2; i += THREADS) sWp[i] = gw[i];
        if (tid < 32) sB[tid] = g_bpack[tid];
    }

    // ---- Phase 1: gather + build features ----
    const int e0  = blockIdx.x * TILE_E;
    const int ee  = tid >> 1;
    const int hlf = tid & 1;
    const int e   = e0 + ee;

    if (e < E) {
        long long n0, n1, n2, n3;
        if (g_nbr64) {
            const long long* nb = (const long long*)nbr_raw + (size_t)e * 4;
            n0 = nb[0]; n1 = nb[1]; n2 = nb[2]; n3 = nb[3];
        } else {
            const int* nb = (const int*)nbr_raw + (size_t)e * 4;
            n0 = nb[0]; n1 = nb[1]; n2 = nb[2]; n3 = nb[3];
        }
        // clamp to valid range (zero-mask handles n<0 per reference semantics;
        // clamp also guards against any residual dtype surprise)
        long long s0 = n0 < 0 ? 0 : (n0 >= E ? E - 1 : n0);
        long long s1 = n1 < 0 ? 0 : (n1 >= E ? E - 1 : n1);
        long long s2 = n2 < 0 ? 0 : (n2 >= E ? E - 1 : n2);
        long long s3 = n3 < 0 ? 0 : (n3 >= E ? E - 1 : n3);

        const float4* xr  = (const float4*)(x + (size_t)e  * 32 + hlf * 16);
        const float4* a0r = (const float4*)(x + (size_t)s0 * 32 + hlf * 16);
        const float4* a1r = (const float4*)(x + (size_t)s1 * 32 + hlf * 16);
        const float4* b0r = (const float4*)(x + (size_t)s2 * 32 + hlf * 16);
        const float4* b1r = (const float4*)(x + (size_t)s3 * 32 + hlf * 16);
        const float4 z = make_float4(0.f, 0.f, 0.f, 0.f);

        float* frow = feat + ee * FSTRIDE + hlf * 16;

        #pragma unroll
        for (int q = 0; q < 4; q++) {
            float4 xv = xr[q];
            float4 A0 = (n0 >= 0) ? a0r[q] : z;
            float4 A1 = (n1 >= 0) ? a1r[q] : z;
            float4 B0 = (n2 >= 0) ? b0r[q] : z;
            float4 B1 = (n3 >= 0) ? b1r[q] : z;

            float sa_x = A0.x + A1.x, da_x = fabsf(A0.x - A1.x);
            float sa_y = A0.y + A1.y, da_y = fabsf(A0.y - A1.y);
            float sa_z = A0.z + A1.z, da_z = fabsf(A0.z - A1.z);
            float sa_w = A0.w + A1.w, da_w = fabsf(A0.w - A1.w);
            float sb_x = B0.x + B1.x, db_x = fabsf(B0.x - B1.x);
            float sb_y = B0.y + B1.y, db_y = fabsf(B0.y - B1.y);
            float sb_z = B0.z + B1.z, db_z = fabsf(B0.z - B1.z);
            float sb_w = B0.w + B1.w, db_w = fabsf(B0.w - B1.w);

            float* p = frow + q * 4;
            ((float2*)(p + 0))[0]   = make_float2(xv.x, xv.y);
            ((float2*)(p + 2))[0]   = make_float2(xv.z, xv.w);
            ((float2*)(p + 32))[0]  = make_float2(sa_x + sb_x, sa_y + sb_y);
            ((float2*)(p + 34))[0]  = make_float2(sa_z + sb_z, sa_w + sb_w);
            ((float2*)(p + 64))[0]  = make_float2(da_x + db_x, da_y + db_y);
            ((float2*)(p + 66))[0]  = make_float2(da_z + db_z, da_w + db_w);
            ((float2*)(p + 96))[0]  = make_float2(fabsf(sa_x - sb_x), fabsf(sa_y - sb_y));
            ((float2*)(p + 98))[0]  = make_float2(fabsf(sa_z - sb_z), fabsf(sa_w - sb_w));
            ((float2*)(p + 128))[0] = make_float2(fabsf(da_x - db_x), fabsf(da_y - db_y));
            ((float2*)(p + 130))[0] = make_float2(fabsf(da_z - db_z), fabsf(da_w - db_w));
        }
    }

    __syncthreads();

    // ---- Phase 2: tiled GEMM feat[128,160] @ Wt[160,64] ----
    const int to = tid & 7;
    const int te = tid >> 3;

    unsigned long long acc[4][4];
    {
        const unsigned long long* bb = (const unsigned long long*)(sB + to * 4);
        unsigned long long b0 = bb[0], b1 = bb[1], b2 = bb[2], b3 = bb[3];
        #pragma unroll
        for (int i = 0; i < 4; i++) {
            acc[i][0] = b0; acc[i][1] = b1; acc[i][2] = b2; acc[i][3] = b3;
        }
    }

    const float* fr0 = feat + (te * 4 + 0) * FSTRIDE;
    const float* fr1 = feat + (te * 4 + 1) * FSTRIDE;
    const float* fr2 = feat + (te * 4 + 2) * FSTRIDE;
    const float* fr3 = feat + (te * 4 + 3) * FSTRIDE;

    #pragma unroll 4
    for (int k = 0; k < NK; k += 2) {
        const unsigned long long* w0 =
            (const unsigned long long*)(sWp + (k + 0) * 32 + to * 4);
        const unsigned long long* w1 =
            (const unsigned long long*)(sWp + (k + 1) * 32 + to * 4);
        unsigned long long wa0 = w0[0], wa1 = w0[1], wa2 = w0[2], wa3 = w0[3];
        unsigned long long wb0 = w1[0], wb1 = w1[1], wb2 = w1[2], wb3 = w1[3];

        float2 f0 = *(const float2*)(fr0 + k);
        float2 f1 = *(const float2*)(fr1 + k);
        float2 f2 = *(const float2*)(fr2 + k);
        float2 f3 = *(const float2*)(fr3 + k);

        unsigned long long fa, fb;
        fa = pack2(f0.x, f0.x); fb = pack2(f0.y, f0.y);
        acc[0][0] = ffma2(fa, wa0, acc[0][0]); acc[0][1] = ffma2(fa, wa1, acc[0][1]);
        acc[0][2] = ffma2(fa, wa2, acc[0][2]); acc[0][3] = ffma2(fa, wa3, acc[0][3]);
        acc[0][0] = ffma2(fb, wb0, acc[0][0]); acc[0][1] = ffma2(fb, wb1, acc[0][1]);
        acc[0][2] = ffma2(fb, wb2, acc[0][2]); acc[0][3] = ffma2(fb, wb3, acc[0][3]);

        fa = pack2(f1.x, f1.x); fb = pack2(f1.y, f1.y);
        acc[1][0] = ffma2(fa, wa0, acc[1][0]); acc[1][1] = ffma2(fa, wa1, acc[1][1]);
        acc[1][2] = ffma2(fa, wa2, acc[1][2]); acc[1][3] = ffma2(fa, wa3, acc[1][3]);
        acc[1][0] = ffma2(fb, wb0, acc[1][0]); acc[1][1] = ffma2(fb, wb1, acc[1][1]);
        acc[1][2] = ffma2(fb, wb2, acc[1][2]); acc[1][3] = ffma2(fb, wb3, acc[1][3]);

        fa = pack2(f2.x, f2.x); fb = pack2(f2.y, f2.y);
        acc[2][0] = ffma2(fa, wa0, acc[2][0]); acc[2][1] = ffma2(fa, wa1, acc[2][1]);
        acc[2][2] = ffma2(fa, wa2, acc[2][2]); acc[2][3] = ffma2(fa, wa3, acc[2][3]);
        acc[2][0] = ffma2(fb, wb0, acc[2][0]); acc[2][1] = ffma2(fb, wb1, acc[2][1]);
        acc[2][2] = ffma2(fb, wb2, acc[2][2]); acc[2][3] = ffma2(fb, wb3, acc[2][3]);

        fa = pack2(f3.x, f3.x); fb = pack2(f3.y, f3.y);
        acc[3][0] = ffma2(fa, wa0, acc[3][0]); acc[3][1] = ffma2(fa, wa1, acc[3][1]);
        acc[3][2] = ffma2(fa, wa2, acc[3][2]); acc[3][3] = ffma2(fa, wa3, acc[3][3]);
        acc[3][0] = ffma2(fb, wb0, acc[3][0]); acc[3][1] = ffma2(fb, wb1, acc[3][1]);
        acc[3][2] = ffma2(fb, wb2, acc[3][2]); acc[3][3] = ffma2(fb, wb3, acc[3][3]);
    }

    // ---- store ----
    #pragma unroll
    for (int i = 0; i < 4; i++) {
        int eo = e0 + te * 4 + i;
        if (eo < E) {
            float2 a0 = u2f2(acc[i][0]);
            float2 a1 = u2f2(acc[i][1]);
            float2 a2 = u2f2(acc[i][2]);
            float2 a3 = u2f2(acc[i][3]);
            float4* op = (float4*)(out + (size_t)eo * 64 + to * 8);
            op[0] = make_float4(a0.x, a0.y, a1.x, a1.y);
            op[1] = make_float4(a2.x, a2.y, a3.x, a3.y);
        }
    }
}

extern "C" void kernel_launch(void* const* d_in, const int* in_sizes, int n_in,
                              void* d_out, int out_size) {
    // Identify inputs by element count (robust to metadata ordering):
    //   x: 32*E, neighbors: 4*E, W: 64*160=10240, b: 64
    const int E = out_size / 64;
    const float* x   = nullptr;
    const void*  nbr = nullptr;
    const float* W   = nullptr;
    const float* b   = nullptr;

    for (int i = 0; i < n_in; i++) {
        long long sz = in_sizes[i];
        if (sz == (long long)E * 32)      x   = (const float*)d_in[i];
        else if (sz == (long long)E * 4)  nbr = d_in[i];
        else if (sz == 64 * NK)           W   = (const float*)d_in[i];
        else if (sz == 64)                b   = (const float*)d_in[i];
    }

    float* out = (float*)d_out;

    meshconv_prep<<<(WP_F2 + 255) / 256, 256>>>(W, b, nbr, E);

    size_t smemB = (size_t)(10304 + TILE_E * FSTRIDE) * sizeof(float);  // ~124 KB
    cudaFuncSetAttribute(meshconv_kernel,
                         cudaFuncAttributeMaxDynamicSharedMemorySize, (int)smemB);

    int nb = (E + TILE_E - 1) / TILE_E;
    meshconv_kernel<<<nb, THREADS, smemB>>>(x, nbr, out, E);
}

// round 4
// speedup vs baseline: 1.2160x; 1.2160x over previous
#include <cuda_runtime.h>
#include <cstdint>

// MeshConv: out[e][o] = sum_k combined[e][k] * W[o][k] + b[o]
// combined = [ x(32) | sa+sb(32) | da+db(32) | |sa-sb|(32) | |da-db|(32) ]

#define TILE_E  256
#define THREADS 512
#define FSTRIDE 162   // feat row stride in floats (4-row spacing = 32B mod 128 -> conflict-free)
#define NK      160
#define WP_F2   (NK * 32)   // 5120 float2

// W packed: float2 index ((k*2+q)*8 + to)*2 + j  ->  (W[o][k], W[o+1][k]),
// o = to*8 + 2*(2q+j). Each 128B row = {to 0..7} x uint4 -> conflict-free LDS.128.
__device__ float2 g_Wpack[WP_F2];
__device__ float2 g_bpack[32];
__device__ int    g_nbr64;

__global__ void meshconv_prep(const float* __restrict__ W, const float* __restrict__ b,
                              const void* __restrict__ nbr_raw, int E) {
    int i = blockIdx.x * blockDim.x + threadIdx.x;
    if (i < WP_F2) {
        int j  = i & 1;
        int to = (i >> 1) & 7;
        int q  = (i >> 4) & 1;
        int k  = i >> 5;
        int o  = to * 8 + 2 * (2 * q + j);
        g_Wpack[i] = make_float2(W[o * NK + k], W[(o + 1) * NK + k]);
    }
    if (i < 32) g_bpack[i] = make_float2(b[2 * i], b[2 * i + 1]);
    if (i == 0) {
        const long long* p = (const long long*)nbr_raw;
        int ok = 1;
        #pragma unroll
        for (int j = 0; j < 16; j++) {
            long long v = p[j];
            if (v < -(long long)E || v >= (long long)E) ok = 0;
        }
        g_nbr64 = ok;
    }
}

__device__ __forceinline__ unsigned long long pack2(float lo, float hi) {
    unsigned long long r;
    asm("mov.b64 %0, {%1, %2};" : "=l"(r) : "f"(lo), "f"(hi));
    return r;
}
__device__ __forceinline__ unsigned long long ffma2(unsigned long long a,
                                                    unsigned long long b,
                                                    unsigned long long c) {
    unsigned long long d;
    asm("fma.rn.f32x2 %0, %1, %2, %3;" : "=l"(d) : "l"(a), "l"(b), "l"(c));
    return d;
}
__device__ __forceinline__ float2 u2f2(unsigned long long u) {
    float2 f;
    f.x = __uint_as_float((unsigned)(u & 0xFFFFFFFFull));
    f.y = __uint_as_float((unsigned)(u >> 32));
    return f;
}

__global__ __launch_bounds__(THREADS, 1)
void meshconv_kernel(const float* __restrict__ x,
                     const void* __restrict__ nbr_raw,
                     float* __restrict__ out, int E) {
    extern __shared__ float smem[];
    // floats: [0,10240) W ; [10240,10304) bias ; [10304, 10304+TILE_E*FSTRIDE) feat
    const ulonglong2* sW2 = (const ulonglong2*)smem;   // index (k*2+q)*8 + to
    float2* sB   = (float2*)(smem + 10240);
    float*  feat = smem + 10304;

    const int tid = threadIdx.x;

    {
        const float2* gw = g_Wpack;
        float2* sw = (float2*)smem;
        #pragma unroll
        for (int i = tid; i < WP_F2; i += THREADS) sw[i] = gw[i];
        if (tid < 32) sB[tid] = g_bpack[tid];
    }

    // ---- Phase 1: gather + build features ----
    const int e0  = blockIdx.x * TILE_E;
    const int ee  = tid >> 1;
    const int hlf = tid & 1;
    const int e   = e0 + ee;

    if (e < E) {
        long long n0, n1, n2, n3;
        if (g_nbr64) {
            const long long* nb = (const long long*)nbr_raw + (size_t)e * 4;
            n0 = nb[0]; n1 = nb[1]; n2 = nb[2]; n3 = nb[3];
        } else {
            const int* nb = (const int*)nbr_raw + (size_t)e * 4;
            n0 = nb[0]; n1 = nb[1]; n2 = nb[2]; n3 = nb[3];
        }
        long long s0 = n0 < 0 ? 0 : (n0 >= E ? E - 1 : n0);
        long long s1 = n1 < 0 ? 0 : (n1 >= E ? E - 1 : n1);
        long long s2 = n2 < 0 ? 0 : (n2 >= E ? E - 1 : n2);
        long long s3 = n3 < 0 ? 0 : (n3 >= E ? E - 1 : n3);

        const float4* xr  = (const float4*)(x + (size_t)e  * 32 + hlf * 16);
        const float4* a0r = (const float4*)(x + (size_t)s0 * 32 + hlf * 16);
        const float4* a1r = (const float4*)(x + (size_t)s1 * 32 + hlf * 16);
        const float4* b0r = (const float4*)(x + (size_t)s2 * 32 + hlf * 16);
        const float4* b1r = (const float4*)(x + (size_t)s3 * 32 + hlf * 16);
        const float4 z = make_float4(0.f, 0.f, 0.f, 0.f);

        float* frow = feat + ee * FSTRIDE + hlf * 16;

        #pragma unroll
        for (int q = 0; q < 4; q++) {
            float4 xv = xr[q];
            float4 A0 = (n0 >= 0) ? a0r[q] : z;
            float4 A1 = (n1 >= 0) ? a1r[q] : z;
            float4 B0 = (n2 >= 0) ? b0r[q] : z;
            float4 B1 = (n3 >= 0) ? b1r[q] : z;

            float sa_x = A0.x + A1.x, da_x = fabsf(A0.x - A1.x);
            float sa_y = A0.y + A1.y, da_y = fabsf(A0.y - A1.y);
            float sa_z = A0.z + A1.z, da_z = fabsf(A0.z - A1.z);
            float sa_w = A0.w + A1.w, da_w = fabsf(A0.w - A1.w);
            float sb_x = B0.x + B1.x, db_x = fabsf(B0.x - B1.x);
            float sb_y = B0.y + B1.y, db_y = fabsf(B0.y - B1.y);
            float sb_z = B0.z + B1.z, db_z = fabsf(B0.z - B1.z);
            float sb_w = B0.w + B1.w, db_w = fabsf(B0.w - B1.w);

            float* p = frow + q * 4;
            ((float2*)(p + 0))[0]   = make_float2(xv.x, xv.y);
            ((float2*)(p + 2))[0]   = make_float2(xv.z, xv.w);
            ((float2*)(p + 32))[0]  = make_float2(sa_x + sb_x, sa_y + sb_y);
            ((float2*)(p + 34))[0]  = make_float2(sa_z + sb_z, sa_w + sb_w);
            ((float2*)(p + 64))[0]  = make_float2(da_x + db_x, da_y + db_y);
            ((float2*)(p + 66))[0]  = make_float2(da_z + db_z, da_w + db_w);
            ((float2*)(p + 96))[0]  = make_float2(fabsf(sa_x - sb_x), fabsf(sa_y - sb_y));
            ((float2*)(p + 98))[0]  = make_float2(fabsf(sa_z - sb_z), fabsf(sa_w - sb_w));
            ((float2*)(p + 128))[0] = make_float2(fabsf(da_x - db_x), fabsf(da_y - db_y));
            ((float2*)(p + 130))[0] = make_float2(fabsf(da_z - db_z), fabsf(da_w - db_w));
        }
    }

    __syncthreads();

    // ---- Phase 2: feat[256,160] @ Wt[160,64]; thread = 4 elems x 8 outs ----
    const int to = tid & 7;
    const int te = tid >> 3;   // 0..63

    unsigned long long acc[4][4];
    {
        const unsigned long long* bb = (const unsigned long long*)(sB + to * 4);
        unsigned long long b0 = bb[0], b1 = bb[1], b2 = bb[2], b3 = bb[3];
        #pragma unroll
        for (int i = 0; i < 4; i++) {
            acc[i][0] = b0; acc[i][1] = b1; acc[i][2] = b2; acc[i][3] = b3;
        }
    }

    const float* fr0 = feat + (te * 4 + 0) * FSTRIDE;
    const float* fr1 = feat + (te * 4 + 1) * FSTRIDE;
    const float* fr2 = feat + (te * 4 + 2) * FSTRIDE;
    const float* fr3 = feat + (te * 4 + 3) * FSTRIDE;

    #pragma unroll 4
    for (int k = 0; k < NK; k += 2) {
        // conflict-free 128B-row W loads (LDS.128)
        ulonglong2 w00 = sW2[((k + 0) * 2 + 0) * 8 + to];
        ulonglong2 w01 = sW2[((k + 0) * 2 + 1) * 8 + to];
        ulonglong2 w10 = sW2[((k + 1) * 2 + 0) * 8 + to];
        ulonglong2 w11 = sW2[((k + 1) * 2 + 1) * 8 + to];

        float2 f0 = *(const float2*)(fr0 + k);
        float2 f1 = *(const float2*)(fr1 + k);
        float2 f2 = *(const float2*)(fr2 + k);
        float2 f3 = *(const float2*)(fr3 + k);

        unsigned long long fa, fb;
        fa = pack2(f0.x, f0.x); fb = pack2(f0.y, f0.y);
        acc[0][0] = ffma2(fa, w00.x, acc[0][0]); acc[0][1] = ffma2(fa, w00.y, acc[0][1]);
        acc[0][2] = ffma2(fa, w01.x, acc[0][2]); acc[0][3] = ffma2(fa, w01.y, acc[0][3]);
        acc[0][0] = ffma2(fb, w10.x, acc[0][0]); acc[0][1] = ffma2(fb, w10.y, acc[0][1]);
        acc[0][2] = ffma2(fb, w11.x, acc[0][2]); acc[0][3] = ffma2(fb, w11.y, acc[0][3]);

        fa = pack2(f1.x, f1.x); fb = pack2(f1.y, f1.y);
        acc[1][0] = ffma2(fa, w00.x, acc[1][0]); acc[1][1] = ffma2(fa, w00.y, acc[1][1]);
        acc[1][2] = ffma2(fa, w01.x, acc[1][2]); acc[1][3] = ffma2(fa, w01.y, acc[1][3]);
        acc[1][0] = ffma2(fb, w10.x, acc[1][0]); acc[1][1] = ffma2(fb, w10.y, acc[1][1]);
        acc[1][2] = ffma2(fb, w11.x, acc[1][2]); acc[1][3] = ffma2(fb, w11.y, acc[1][3]);

        fa = pack2(f2.x, f2.x); fb = pack2(f2.y, f2.y);
        acc[2][0] = ffma2(fa, w00.x, acc[2][0]); acc[2][1] = ffma2(fa, w00.y, acc[2][1]);
        acc[2][2] = ffma2(fa, w01.x, acc[2][2]); acc[2][3] = ffma2(fa, w01.y, acc[2][3]);
        acc[2][0] = ffma2(fb, w10.x, acc[2][0]); acc[2][1] = ffma2(fb, w10.y, acc[2][1]);
        acc[2][2] = ffma2(fb, w11.x, acc[2][2]); acc[2][3] = ffma2(fb, w11.y, acc[2][3]);

        fa = pack2(f3.x, f3.x); fb = pack2(f3.y, f3.y);
        acc[3][0] = ffma2(fa, w00.x, acc[3][0]); acc[3][1] = ffma2(fa, w00.y, acc[3][1]);
        acc[3][2] = ffma2(fa, w01.x, acc[3][2]); acc[3][3] = ffma2(fa, w01.y, acc[3][3]);
        acc[3][0] = ffma2(fb, w10.x, acc[3][0]); acc[3][1] = ffma2(fb, w10.y, acc[3][1]);
        acc[3][2] = ffma2(fb, w11.x, acc[3][2]); acc[3][3] = ffma2(fb, w11.y, acc[3][3]);
    }

    // ---- store ----
    #pragma unroll
    for (int i = 0; i < 4; i++) {
        int eo = e0 + te * 4 + i;
        if (eo < E) {
            float2 a0 = u2f2(acc[i][0]);
            float2 a1 = u2f2(acc[i][1]);
            float2 a2 = u2f2(acc[i][2]);
            float2 a3 = u2f2(acc[i][3]);
            float4* op = (float4*)(out + (size_t)eo * 64 + to * 8);
            op[0] = make_float4(a0.x, a0.y, a1.x, a1.y);
            op[1] = make_float4(a2.x, a2.y, a3.x, a3.y);
        }
    }
}

extern "C" void kernel_launch(void* const* d_in, const int* in_sizes, int n_in,
                              void* d_out, int out_size) {
    const int E = out_size / 64;
    const float* x   = nullptr;
    const void*  nbr = nullptr;
    const float* W   = nullptr;
    const float* b   = nullptr;

    for (int i = 0; i < n_in; i++) {
        long long sz = in_sizes[i];
        if (sz == (long long)E * 32)      x   = (const float*)d_in[i];
        else if (sz == (long long)E * 4)  nbr = d_in[i];
        else if (sz == 64 * NK)           W   = (const float*)d_in[i];
        else if (sz == 64)                b   = (const float*)d_in[i];
    }

    float* out = (float*)d_out;

    meshconv_prep<<<(WP_F2 + 255) / 256, 256>>>(W, b, nbr, E);

    size_t smemB = (size_t)(10304 + TILE_E * FSTRIDE) * sizeof(float);  // ~207 KB
    cudaFuncSetAttribute(meshconv_kernel,
                         cudaFuncAttributeMaxDynamicSharedMemorySize, (int)smemB);

    int nb = (E + TILE_E - 1) / TILE_E;
    meshconv_kernel<<<nb, THREADS, smemB>>>(x, nbr, out, E);
}

// round 6
// speedup vs baseline: 1.5559x; 1.2796x over previous
#include <cuda_runtime.h>
#include <cuda_bf16.h>
#include <cstdint>

// MeshConv via mma.sync m16n8k16 bf16 (split hi/lo for fp32 accuracy).
// out[e][o] = sum_k feat[e][k] * W[o][k] + b[o], K=160=10x16, N=64, tile M=256.

#define NK      160
#define TILE_E  256
#define THREADS 256
#define RSTRIDE 336            // bytes per feature row (21 x 16B chunks; 20 used)
#define A_BYTES (TILE_E * RSTRIDE)          // 86016 per split
#define WF_U4   (10 * 8 * 32)               // k-steps x n-steps x lanes
#define SM_AHI  0
#define SM_ALO  A_BYTES
#define SM_WF   (2 * A_BYTES)
#define SM_TOTAL (2 * A_BYTES + WF_U4 * 16) // 212992 B

__device__ uint4 g_Wfrag[WF_U4];
__device__ int   g_nbr64;

__device__ __forceinline__ uint32_t pk_bf16x2(float lo, float hi) {
    uint32_t r;
    asm("cvt.rn.satfinite.bf16x2.f32 %0, %1, %2;" : "=r"(r) : "f"(hi), "f"(lo));
    return r;  // low half = lo, high half = hi
}

__global__ void meshconv_prep(const float* __restrict__ W,
                              const void* __restrict__ nbr_raw, int E) {
    int i = blockIdx.x * blockDim.x + threadIdx.x;
    if (i < WF_U4) {
        // PTX m16n8k16 B-fragment (col-major k16n8): lane l holds
        //   b0: k=(l%4)*2,+1  n=l/4 ;  b1: k=(l%4)*2+8,+1  n=l/4
        int lane = i & 31;
        int n    = (i >> 5) & 7;
        int ks   = i >> 8;
        int ng = n * 8 + (lane >> 2);
        int k0 = ks * 16 + (lane & 3) * 2;
        float w00 = W[ng * NK + k0],     w01 = W[ng * NK + k0 + 1];
        float w10 = W[ng * NK + k0 + 8], w11 = W[ng * NK + k0 + 9];
        float h00 = __bfloat162float(__float2bfloat16(w00));
        float h01 = __bfloat162float(__float2bfloat16(w01));
        float h10 = __bfloat162float(__float2bfloat16(w10));
        float h11 = __bfloat162float(__float2bfloat16(w11));
        uint4 f;
        f.x = pk_bf16x2(h00, h01);              // B_hi reg0
        f.y = pk_bf16x2(h10, h11);              // B_hi reg1
        f.z = pk_bf16x2(w00 - h00, w01 - h01);  // B_lo reg0
        f.w = pk_bf16x2(w10 - h10, w11 - h11);  // B_lo reg1
        g_Wfrag[i] = f;
    }
    if (i == 0) {
        const long long* p = (const long long*)nbr_raw;
        int ok = 1;
        #pragma unroll
        for (int j = 0; j < 16; j++) {
            long long v = p[j];
            if (v < -(long long)E || v >= (long long)E) ok = 0;
        }
        g_nbr64 = ok;
    }
}

__device__ __forceinline__ uint32_t smem_u32(const void* p) {
    uint32_t a;
    asm("{ .reg .u64 t; cvta.to.shared.u64 t, %1; cvt.u32.u64 %0, t; }" : "=r"(a) : "l"(p));
    return a;
}
__device__ __forceinline__ void ldsm_x4(uint32_t* r, uint32_t addr) {
    asm volatile("ldmatrix.sync.aligned.m8n8.x4.shared.b16 {%0,%1,%2,%3}, [%4];"
                 : "=r"(r[0]), "=r"(r[1]), "=r"(r[2]), "=r"(r[3]) : "r"(addr));
}
__device__ __forceinline__ void mma_bf16(float* d, const uint32_t* a,
                                         uint32_t b0, uint32_t b1) {
    asm volatile(
        "mma.sync.aligned.m16n8k16.row.col.f32.bf16.bf16.f32 "
        "{%0,%1,%2,%3}, {%4,%5,%6,%7}, {%8,%9}, {%0,%1,%2,%3};"
        : "+f"(d[0]), "+f"(d[1]), "+f"(d[2]), "+f"(d[3])
        : "r"(a[0]), "r"(a[1]), "r"(a[2]), "r"(a[3]), "r"(b0), "r"(b1));
}

__global__ __launch_bounds__(THREADS, 1)
void meshconv_kernel(const float* __restrict__ x,
                     const void* __restrict__ nbr_raw,
                     const float* __restrict__ bias,
                     float* __restrict__ out, int E) {
    extern __shared__ char smem[];
    const uint32_t sbase = smem_u32(smem);
    const int tid  = threadIdx.x;
    const int lane = tid & 31;
    const int warp = tid >> 5;

    // ---- copy W fragments into smem (coalesced) ----
    {
        uint4* dst = (uint4*)(smem + SM_WF);
        #pragma unroll
        for (int i = tid; i < WF_U4; i += THREADS) dst[i] = g_Wfrag[i];
    }

    // ---- Phase 1: gather + features -> split bf16 -> smem A (hi/lo) ----
    const int e0 = blockIdx.x * TILE_E;
    const int e  = e0 + tid;
    const int er = e < E ? e : (E - 1);

    long long n[4];
    if (g_nbr64) {
        const long long* nb = (const long long*)nbr_raw + (size_t)er * 4;
        n[0] = nb[0]; n[1] = nb[1]; n[2] = nb[2]; n[3] = nb[3];
    } else {
        const int* nb = (const int*)nbr_raw + (size_t)er * 4;
        n[0] = nb[0]; n[1] = nb[1]; n[2] = nb[2]; n[3] = nb[3];
    }
    float m[4];
    long long s[4];
    #pragma unroll
    for (int j = 0; j < 4; j++) {
        m[j] = (n[j] >= 0) ? 1.0f : 0.0f;
        long long v = n[j] < 0 ? 0 : n[j];
        s[j] = v >= E ? (long long)(E - 1) : v;
    }
    const float* xr = x + (size_t)er * 32;
    const float* r0 = x + (size_t)s[0] * 32;
    const float* r1 = x + (size_t)s[1] * 32;
    const float* r2 = x + (size_t)s[2] * 32;
    const float* r3 = x + (size_t)s[3] * 32;

    char* aHi = smem + SM_AHI + tid * RSTRIDE;
    char* aLo = smem + SM_ALO + tid * RSTRIDE;

    #pragma unroll
    for (int p = 0; p < 4; p++) {          // 8 channels per iter
        float xv[8], A0[8], A1[8], B0[8], B1[8];
        {
            float4 t0 = *(const float4*)(xr + p * 8);
            float4 t1 = *(const float4*)(xr + p * 8 + 4);
            xv[0]=t0.x; xv[1]=t0.y; xv[2]=t0.z; xv[3]=t0.w;
            xv[4]=t1.x; xv[5]=t1.y; xv[6]=t1.z; xv[7]=t1.w;
        }
        #define LOAD8(dst, src, mm) { \
            float4 t0 = *(const float4*)((src) + p * 8); \
            float4 t1 = *(const float4*)((src) + p * 8 + 4); \
            dst[0]=t0.x*(mm); dst[1]=t0.y*(mm); dst[2]=t0.z*(mm); dst[3]=t0.w*(mm); \
            dst[4]=t1.x*(mm); dst[5]=t1.y*(mm); dst[6]=t1.z*(mm); dst[7]=t1.w*(mm); }
        LOAD8(A0, r0, m[0]); LOAD8(A1, r1, m[1]);
        LOAD8(B0, r2, m[2]); LOAD8(B1, r3, m[3]);
        #undef LOAD8

        float v[5][8];
        #pragma unroll
        for (int j = 0; j < 8; j++) {
            float sa = A0[j] + A1[j], sb = B0[j] + B1[j];
            float da = fabsf(A0[j] - A1[j]), db = fabsf(B0[j] - B1[j]);
            v[0][j] = xv[j];
            v[1][j] = sa + sb;
            v[2][j] = da + db;
            v[3][j] = fabsf(sa - sb);
            v[4][j] = fabsf(da - db);
        }

        #pragma unroll
        for (int g = 0; g < 5; g++) {
            uint32_t hi[4], lo[4];
            #pragma unroll
            for (int t = 0; t < 4; t++) {
                float ve = v[g][2 * t], vo = v[g][2 * t + 1];
                uint32_t h = pk_bf16x2(ve, vo);
                float he = __uint_as_float(h << 16);
                float ho = __uint_as_float(h & 0xFFFF0000u);
                hi[t] = h;
                lo[t] = pk_bf16x2(ve - he, vo - ho);
            }
            int chunk = 4 * g + p;          // k = g*32 + p*8 .. +7
            *(uint4*)(aHi + chunk * 16) = make_uint4(hi[0], hi[1], hi[2], hi[3]);
            *(uint4*)(aLo + chunk * 16) = make_uint4(lo[0], lo[1], lo[2], lo[3]);
        }
    }
    __syncthreads();

    // ---- Phase 2: MMA. warp owns rows [warp*32, warp*32+32) ----
    float acc[2][8][4];
    #pragma unroll
    for (int st = 0; st < 2; st++)
        #pragma unroll
        for (int nn = 0; nn < 8; nn++)
            #pragma unroll
            for (int q = 0; q < 4; q++) acc[st][nn][q] = 0.0f;

    // ldmatrix row/chunk mapping: row = base + (lane&15); +16B for lanes>=16
    const uint32_t arow = (uint32_t)(warp * 32 + (lane & 15));
    const uint32_t aoff = ((uint32_t)(lane >> 4)) * 16;
    const uint32_t ahi0 = sbase + SM_AHI + arow * RSTRIDE + aoff;
    const uint32_t ahi1 = ahi0 + 16 * RSTRIDE;
    const uint32_t alo0 = sbase + SM_ALO + arow * RSTRIDE + aoff;
    const uint32_t alo1 = alo0 + 16 * RSTRIDE;
    const uint4* wf = (const uint4*)(smem + SM_WF);

    #pragma unroll
    for (int ks = 0; ks < 10; ks++) {
        uint32_t fh0[4], fh1[4], fl0[4], fl1[4];
        ldsm_x4(fh0, ahi0 + ks * 32);
        ldsm_x4(fh1, ahi1 + ks * 32);
        ldsm_x4(fl0, alo0 + ks * 32);
        ldsm_x4(fl1, alo1 + ks * 32);
        #pragma unroll
        for (int nn = 0; nn < 8; nn++) {
            uint4 f = wf[(ks * 8 + nn) * 32 + lane];
            mma_bf16(acc[0][nn], fh0, f.x, f.y);   // Ahi*Bhi
            mma_bf16(acc[0][nn], fh0, f.z, f.w);   // Ahi*Blo
            mma_bf16(acc[0][nn], fl0, f.x, f.y);   // Alo*Bhi
            mma_bf16(acc[1][nn], fh1, f.x, f.y);
            mma_bf16(acc[1][nn], fh1, f.z, f.w);
            mma_bf16(acc[1][nn], fl1, f.x, f.y);
        }
    }

    // ---- Epilogue: D fragment + bias -> gmem ----
    const int colq = (lane & 3) * 2;       // col within n8 chunk
    #pragma unroll
    for (int nn = 0; nn < 8; nn++) {
        int col = nn * 8 + colq;
        float2 bv = *(const float2*)(bias + col);
        #pragma unroll
        for (int st = 0; st < 2; st++) {
            int rbase = e0 + warp * 32 + st * 16 + (lane >> 2);
            if (rbase < E) {
                float2 o0 = make_float2(acc[st][nn][0] + bv.x, acc[st][nn][1] + bv.y);
                *(float2*)(out + (size_t)rbase * 64 + col) = o0;
            }
            if (rbase + 8 < E) {
                float2 o1 = make_float2(acc[st][nn][2] + bv.x, acc[st][nn][3] + bv.y);
                *(float2*)(out + (size_t)(rbase + 8) * 64 + col) = o1;
            }
        }
    }
}

extern "C" void kernel_launch(void* const* d_in, const int* in_sizes, int n_in,
                              void* d_out, int out_size) {
    const int E = out_size / 64;
    const float* x = nullptr; const void* nbr = nullptr;
    const float* W = nullptr; const float* b = nullptr;

    for (int i = 0; i < n_in; i++) {
        long long sz = in_sizes[i];
        if (sz == (long long)E * 32)      x   = (const float*)d_in[i];
        else if (sz == (long long)E * 4)  nbr = d_in[i];
        else if (sz == 64 * NK)           W   = (const float*)d_in[i];
        else if (sz == 64)                b   = (const float*)d_in[i];
    }
    float* out = (float*)d_out;

    meshconv_prep<<<(WF_U4 + 255) / 256, 256>>>(W, nbr, E);

    cudaFuncSetAttribute(meshconv_kernel,
                         cudaFuncAttributeMaxDynamicSharedMemorySize, SM_TOTAL);
    int nb = (E + TILE_E - 1) / TILE_E;
    meshconv_kernel<<<nb, THREADS, SM_TOTAL>>>(x, nbr, b, out, E);
}

// round 7
// speedup vs baseline: 2.2692x; 1.4584x over previous
#include <cuda_runtime.h>
#include <cuda_bf16.h>
#include <cstdint>

// MeshConv via mma.sync m16n8k16 bf16 split hi/lo (3-term). Warp-independent:
// warp w gathers+builds rows [32w,32w+32), __syncwarp, MMAs its own rows.
// W fragments read straight from gmem (L1-resident). No __syncthreads.

#define NK      160
#define TILE_E  128
#define THREADS 128
#define RSTRIDE 336                    // bytes per feature row (21 x 16B chunks)
#define A_BYTES (TILE_E * RSTRIDE)     // 43008 per split
#define SM_AHI  0
#define SM_ALO  A_BYTES
#define SM_TOTAL (2 * A_BYTES)         // 86016 B
#define WF_U4   (10 * 8 * 32)

__device__ uint4 g_Wfrag[WF_U4];
__device__ int   g_nbr64;

__device__ __forceinline__ uint32_t pk_bf16x2(float lo, float hi) {
    uint32_t r;
    asm("cvt.rn.satfinite.bf16x2.f32 %0, %1, %2;" : "=r"(r) : "f"(hi), "f"(lo));
    return r;
}

__global__ void meshconv_prep(const float* __restrict__ W,
                              const void* __restrict__ nbr_raw, int E) {
    int i = blockIdx.x * blockDim.x + threadIdx.x;
    if (i < WF_U4) {
        // m16n8k16 B-fragment: lane l -> b0:k=(l%4)*2(+1),n=l/4 ; b1: k+8
        int lane = i & 31;
        int n    = (i >> 5) & 7;
        int ks   = i >> 8;
        int ng = n * 8 + (lane >> 2);
        int k0 = ks * 16 + (lane & 3) * 2;
        float w00 = W[ng * NK + k0],     w01 = W[ng * NK + k0 + 1];
        float w10 = W[ng * NK + k0 + 8], w11 = W[ng * NK + k0 + 9];
        float h00 = __bfloat162float(__float2bfloat16(w00));
        float h01 = __bfloat162float(__float2bfloat16(w01));
        float h10 = __bfloat162float(__float2bfloat16(w10));
        float h11 = __bfloat162float(__float2bfloat16(w11));
        uint4 f;
        f.x = pk_bf16x2(h00, h01);
        f.y = pk_bf16x2(h10, h11);
        f.z = pk_bf16x2(w00 - h00, w01 - h01);
        f.w = pk_bf16x2(w10 - h10, w11 - h11);
        g_Wfrag[i] = f;
    }
    if (i == 0) {
        const long long* p = (const long long*)nbr_raw;
        int ok = 1;
        #pragma unroll
        for (int j = 0; j < 16; j++) {
            long long v = p[j];
            if (v < -(long long)E || v >= (long long)E) ok = 0;
        }
        g_nbr64 = ok;
    }
}

__device__ __forceinline__ uint32_t smem_u32(const void* p) {
    uint32_t a;
    asm("{ .reg .u64 t; cvta.to.shared.u64 t, %1; cvt.u32.u64 %0, t; }" : "=r"(a) : "l"(p));
    return a;
}
__device__ __forceinline__ void ldsm_x4(uint32_t* r, uint32_t addr) {
    asm volatile("ldmatrix.sync.aligned.m8n8.x4.shared.b16 {%0,%1,%2,%3}, [%4];"
                 : "=r"(r[0]), "=r"(r[1]), "=r"(r[2]), "=r"(r[3]) : "r"(addr));
}
__device__ __forceinline__ void mma_bf16(float* d, const uint32_t* a,
                                         uint32_t b0, uint32_t b1) {
    asm volatile(
        "mma.sync.aligned.m16n8k16.row.col.f32.bf16.bf16.f32 "
        "{%0,%1,%2,%3}, {%4,%5,%6,%7}, {%8,%9}, {%0,%1,%2,%3};"
        : "+f"(d[0]), "+f"(d[1]), "+f"(d[2]), "+f"(d[3])
        : "r"(a[0]), "r"(a[1]), "r"(a[2]), "r"(a[3]), "r"(b0), "r"(b1));
}

__global__ __launch_bounds__(THREADS, 2)
void meshconv_kernel(const float* __restrict__ x,
                     const void* __restrict__ nbr_raw,
                     const float* __restrict__ bias,
                     float* __restrict__ out, int E) {
    extern __shared__ char smem[];
    const uint32_t sbase = smem_u32(smem);
    const int tid  = threadIdx.x;
    const int lane = tid & 31;
    const int warp = tid >> 5;

    // ---- Phase 1 (per-warp): gather + features -> split bf16 -> smem ----
    const int e0 = blockIdx.x * TILE_E;
    const int e  = e0 + tid;
    const int er = e < E ? e : (E - 1);

    long long n[4];
    if (g_nbr64) {
        const long long* nb = (const long long*)nbr_raw + (size_t)er * 4;
        n[0] = nb[0]; n[1] = nb[1]; n[2] = nb[2]; n[3] = nb[3];
    } else {
        const int* nb = (const int*)nbr_raw + (size_t)er * 4;
        n[0] = nb[0]; n[1] = nb[1]; n[2] = nb[2]; n[3] = nb[3];
    }
    float m[4];
    long long s[4];
    #pragma unroll
    for (int j = 0; j < 4; j++) {
        m[j] = (n[j] >= 0) ? 1.0f : 0.0f;
        long long v = n[j] < 0 ? 0 : n[j];
        s[j] = v >= E ? (long long)(E - 1) : v;
    }
    const float* xr = x + (size_t)er * 32;
    const float* r0 = x + (size_t)s[0] * 32;
    const float* r1 = x + (size_t)s[1] * 32;
    const float* r2 = x + (size_t)s[2] * 32;
    const float* r3 = x + (size_t)s[3] * 32;

    char* aHi = smem + SM_AHI + tid * RSTRIDE;
    char* aLo = smem + SM_ALO + tid * RSTRIDE;

    #pragma unroll
    for (int p = 0; p < 4; p++) {
        float xv[8], A0[8], A1[8], B0[8], B1[8];
        {
            float4 t0 = *(const float4*)(xr + p * 8);
            float4 t1 = *(const float4*)(xr + p * 8 + 4);
            xv[0]=t0.x; xv[1]=t0.y; xv[2]=t0.z; xv[3]=t0.w;
            xv[4]=t1.x; xv[5]=t1.y; xv[6]=t1.z; xv[7]=t1.w;
        }
        #define LOAD8(dst, src, mm) { \
            float4 t0 = *(const float4*)((src) + p * 8); \
            float4 t1 = *(const float4*)((src) + p * 8 + 4); \
            dst[0]=t0.x*(mm); dst[1]=t0.y*(mm); dst[2]=t0.z*(mm); dst[3]=t0.w*(mm); \
            dst[4]=t1.x*(mm); dst[5]=t1.y*(mm); dst[6]=t1.z*(mm); dst[7]=t1.w*(mm); }
        LOAD8(A0, r0, m[0]); LOAD8(A1, r1, m[1]);
        LOAD8(B0, r2, m[2]); LOAD8(B1, r3, m[3]);
        #undef LOAD8

        float v[5][8];
        #pragma unroll
        for (int j = 0; j < 8; j++) {
            float sa = A0[j] + A1[j], sb = B0[j] + B1[j];
            float da = fabsf(A0[j] - A1[j]), db = fabsf(B0[j] - B1[j]);
            v[0][j] = xv[j];
            v[1][j] = sa + sb;
            v[2][j] = da + db;
            v[3][j] = fabsf(sa - sb);
            v[4][j] = fabsf(da - db);
        }

        #pragma unroll
        for (int g = 0; g < 5; g++) {
            uint32_t hi[4], lo[4];
            #pragma unroll
            for (int t = 0; t < 4; t++) {
                float ve = v[g][2 * t], vo = v[g][2 * t + 1];
                uint32_t h = pk_bf16x2(ve, vo);
                float he = __uint_as_float(h << 16);
                float ho = __uint_as_float(h & 0xFFFF0000u);
                hi[t] = h;
                lo[t] = pk_bf16x2(ve - he, vo - ho);
            }
            int chunk = 4 * g + p;
            *(uint4*)(aHi + chunk * 16) = make_uint4(hi[0], hi[1], hi[2], hi[3]);
            *(uint4*)(aLo + chunk * 16) = make_uint4(lo[0], lo[1], lo[2], lo[3]);
        }
    }
    __syncwarp();   // warp's own smem rows are all it needs

    // ---- Phase 2 (per-warp): MMA over own 32 rows ----
    float acc[2][8][4];
    #pragma unroll
    for (int st = 0; st < 2; st++)
        #pragma unroll
        for (int nn = 0; nn < 8; nn++)
            #pragma unroll
            for (int q = 0; q < 4; q++) acc[st][nn][q] = 0.0f;

    const uint32_t arow = (uint32_t)(warp * 32 + (lane & 15));
    const uint32_t aoff = ((uint32_t)(lane >> 4)) * 16;
    const uint32_t ahi0 = sbase + SM_AHI + arow * RSTRIDE + aoff;
    const uint32_t ahi1 = ahi0 + 16 * RSTRIDE;
    const uint32_t alo0 = sbase + SM_ALO + arow * RSTRIDE + aoff;
    const uint32_t alo1 = alo0 + 16 * RSTRIDE;

    #pragma unroll
    for (int ks = 0; ks < 10; ks++) {
        uint32_t fh0[4], fh1[4], fl0[4], fl1[4];
        ldsm_x4(fh0, ahi0 + ks * 32);
        ldsm_x4(fh1, ahi1 + ks * 32);
        ldsm_x4(fl0, alo0 + ks * 32);
        ldsm_x4(fl1, alo1 + ks * 32);
        #pragma unroll
        for (int nn = 0; nn < 8; nn++) {
            uint4 f = __ldg(&g_Wfrag[(ks * 8 + nn) * 32 + lane]);
            mma_bf16(acc[0][nn], fh0, f.x, f.y);
            mma_bf16(acc[0][nn], fh0, f.z, f.w);
            mma_bf16(acc[0][nn], fl0, f.x, f.y);
            mma_bf16(acc[1][nn], fh1, f.x, f.y);
            mma_bf16(acc[1][nn], fh1, f.z, f.w);
            mma_bf16(acc[1][nn], fl1, f.x, f.y);
        }
    }

    // ---- Epilogue: D fragment + bias -> gmem ----
    const int colq = (lane & 3) * 2;
    #pragma unroll
    for (int nn = 0; nn < 8; nn++) {
        int col = nn * 8 + colq;
        float2 bv = *(const float2*)(bias + col);
        #pragma unroll
        for (int st = 0; st < 2; st++) {
            int rbase = e0 + warp * 32 + st * 16 + (lane >> 2);
            if (rbase < E) {
                float2 o0 = make_float2(acc[st][nn][0] + bv.x, acc[st][nn][1] + bv.y);
                *(float2*)(out + (size_t)rbase * 64 + col) = o0;
            }
            if (rbase + 8 < E) {
                float2 o1 = make_float2(acc[st][nn][2] + bv.x, acc[st][nn][3] + bv.y);
                *(float2*)(out + (size_t)(rbase + 8) * 64 + col) = o1;
            }
        }
    }
}

extern "C" void kernel_launch(void* const* d_in, const int* in_sizes, int n_in,
                              void* d_out, int out_size) {
    const int E = out_size / 64;
    const float* x = nullptr; const void* nbr = nullptr;
    const float* W = nullptr; const float* b = nullptr;

    for (int i = 0; i < n_in; i++) {
        long long sz = in_sizes[i];
        if (sz == (long long)E * 32)      x   = (const float*)d_in[i];
        else if (sz == (long long)E * 4)  nbr = d_in[i];
        else if (sz == 64 * NK)           W   = (const float*)d_in[i];
        else if (sz == 64)                b   = (const float*)d_in[i];
    }
    float* out = (float*)d_out;

    meshconv_prep<<<(WF_U4 + 255) / 256, 256>>>(W, nbr, E);

    cudaFuncSetAttribute(meshconv_kernel,
                         cudaFuncAttributeMaxDynamicSharedMemorySize, SM_TOTAL);
    int nb = (E + TILE_E - 1) / TILE_E;
    meshconv_kernel<<<nb, THREADS, SM_TOTAL>>>(x, nbr, b, out, E);
}